// round 8
// baseline (speedup 1.0000x reference)
#include <cuda_runtime.h>

// Problem constants
#define NN 50000
#define NE 600000
#define GRIDSZ 296                   // 148 SMs x 2 blocks: guaranteed co-resident
#define NBLK 196                     // ceil(NN/256)

// Float scratch offsets
#define OFF_RS_OUT 0
#define OFF_RS_IN  50000
#define OFF_T1     100000            // 50000*64
#define OFF_AGG1   3300000           // 50000*64
#define OFF_T2     6500000           // 50000*32
#define OFF_T3     8100000           // 50000*32
#define OFF_AGG3   9700000           // 50000*32
#define SCRATCH_TOTAL 11300000       // 45.2 MB

// Int scratch offsets
#define ICNT_SRC 0                   // 50000 out-degree counts
#define ICNT_DST 50000               // 50000 in-degree counts (consumed by fill)
#define IOFFS    100000              // 50001 CSR row offsets
#define ICSR     150004              // 600000 src ids grouped by dst
#define IBSUM    750004              // 196 scan block sums
#define IBASE    750200              // 196 scan block bases (fresh region)
#define INT_TOTAL 750396

__device__ __align__(16) float g_scratch[SCRATCH_TOTAL];
__device__ __align__(16) int   g_int[INT_TOTAL];
__device__ unsigned g_bar_count;     // zero-init; invariant: 0 between barriers
__device__ unsigned g_bar_gen;       // monotonically increasing across replays

// ---------------------------------------------------------------------------
// Software grid barrier. Requires all GRIDSZ blocks co-resident (guaranteed by
// __launch_bounds__(256,2) + grid size). Sense = generation counter.
// ---------------------------------------------------------------------------
__device__ __forceinline__ void grid_sync() {
    __syncthreads();
    if (threadIdx.x == 0) {
        __threadfence();
        unsigned gen = atomicAdd(&g_bar_gen, 0u);      // read BEFORE arriving
        if (atomicAdd(&g_bar_count, 1u) == GRIDSZ - 1u) {
            atomicExch(&g_bar_count, 0u);
            __threadfence();
            atomicAdd(&g_bar_gen, 1u);                 // release
        } else {
            while (atomicAdd(&g_bar_gen, 0u) == gen) __nanosleep(64);
        }
        __threadfence();
    }
    __syncthreads();
}

// ---------------------------------------------------------------------------
// Register-tiled GEMM phase (TN=4 nodes x 8 cols per thread, transposed X
// tile: conflict-free LDS.128 for both W and X). Grid-stride over node tiles.
//   MODE_IN : 0 raw, 1 relu(v*rs_in[n] + bin[k]), 2 v*rs_in[n]
//   MODE_OUT: 0 raw, 1 *rs_out[n],               2 +bout[j]
// ---------------------------------------------------------------------------
template<int K, int J, int KC, int MODE_IN, int MODE_OUT>
__device__ __forceinline__ void gemm_phase(
    const float* __restrict__ X, const float* __restrict__ W,
    const float* __restrict__ rs_in, const float* __restrict__ bin,
    const float* __restrict__ rs_out, const float* __restrict__ bout,
    float* __restrict__ out, float* smem)
{
    constexpr int TN = 4;
    constexpr int JV = J / 8;            // column lanes (8 cols each)
    constexpr int NT = 256 / JV;         // thread rows
    constexpr int NB = NT * TN;          // nodes per tile
    constexpr int NTILES = (NN + NB - 1) / NB;
    float* sW  = smem;                   // KC*J
    float* sX  = smem + KC * J;          // KC*NB, layout [k][node]
    float* sRS = sX + KC * NB;           // NB
    const int nrow = threadIdx.x / JV;
    const int jv   = threadIdx.x % JV;

    for (int tile = blockIdx.x; tile < NTILES; tile += GRIDSZ) {
        const int base = tile * NB;
        __syncthreads();                 // protect smem vs previous tile reads
        if (MODE_OUT == 1 && threadIdx.x < NB) {
            int n = base + threadIdx.x;
            sRS[threadIdx.x] = (n < NN) ? __ldg(&rs_out[n]) : 0.f;
        }
        float4 acc[TN][2];
        #pragma unroll
        for (int t = 0; t < TN; t++)
            #pragma unroll
            for (int c = 0; c < 2; c++)
                acc[t][c] = (MODE_OUT == 2)
                    ? __ldg((const float4*)&bout[8 * jv + 4 * c])
                    : make_float4(0.f, 0.f, 0.f, 0.f);

        #pragma unroll 1
        for (int k0 = 0; k0 < K; k0 += KC) {
            __syncthreads();
            for (int i = threadIdx.x; i < KC * J / 4; i += 256)
                ((float4*)sW)[i] = __ldg(&((const float4*)(W + (size_t)k0 * J))[i]);
            for (int i = threadIdx.x; i < NB * (KC / 4); i += 256) {
                int nl = i % NB;
                int kc = i / NB;
                int n = base + nl;
                float4 v = make_float4(0.f, 0.f, 0.f, 0.f);
                if (n < NN) {
                    v = __ldg((const float4*)&X[(size_t)n * K + k0 + 4 * kc]);
                    if (MODE_IN == 1) {
                        float r = __ldg(&rs_in[n]);
                        float4 b = __ldg((const float4*)&bin[k0 + 4 * kc]);
                        v.x = fmaxf(fmaf(v.x, r, b.x), 0.f);
                        v.y = fmaxf(fmaf(v.y, r, b.y), 0.f);
                        v.z = fmaxf(fmaf(v.z, r, b.z), 0.f);
                        v.w = fmaxf(fmaf(v.w, r, b.w), 0.f);
                    } else if (MODE_IN == 2) {
                        float r = __ldg(&rs_in[n]);
                        v.x *= r; v.y *= r; v.z *= r; v.w *= r;
                    }
                }
                sX[(4 * kc + 0) * NB + nl] = v.x;
                sX[(4 * kc + 1) * NB + nl] = v.y;
                sX[(4 * kc + 2) * NB + nl] = v.z;
                sX[(4 * kc + 3) * NB + nl] = v.w;
            }
            __syncthreads();
            #pragma unroll 4
            for (int k = 0; k < KC; k++) {
                float4 w0 = *(const float4*)&sW[k * J + 8 * jv];
                float4 w1 = *(const float4*)&sW[k * J + 8 * jv + 4];
                float4 xa = *(const float4*)&sX[k * NB + nrow * TN];
                float xk4[4] = {xa.x, xa.y, xa.z, xa.w};
                #pragma unroll
                for (int t = 0; t < TN; t++) {
                    float xk = xk4[t];
                    acc[t][0].x = fmaf(xk, w0.x, acc[t][0].x);
                    acc[t][0].y = fmaf(xk, w0.y, acc[t][0].y);
                    acc[t][0].z = fmaf(xk, w0.z, acc[t][0].z);
                    acc[t][0].w = fmaf(xk, w0.w, acc[t][0].w);
                    acc[t][1].x = fmaf(xk, w1.x, acc[t][1].x);
                    acc[t][1].y = fmaf(xk, w1.y, acc[t][1].y);
                    acc[t][1].z = fmaf(xk, w1.z, acc[t][1].z);
                    acc[t][1].w = fmaf(xk, w1.w, acc[t][1].w);
                }
            }
        }
        #pragma unroll
        for (int t = 0; t < TN; t++) {
            int nl = nrow * TN + t;
            int n = base + nl;
            if (n < NN) {
                if (MODE_OUT == 1) {
                    float r = sRS[nl];
                    #pragma unroll
                    for (int c = 0; c < 2; c++) {
                        acc[t][c].x *= r; acc[t][c].y *= r;
                        acc[t][c].z *= r; acc[t][c].w *= r;
                    }
                }
                *(float4*)&out[(size_t)n * J + 8 * jv]     = acc[t][0];
                *(float4*)&out[(size_t)n * J + 8 * jv + 4] = acc[t][1];
            }
        }
    }
}

// ---------------------------------------------------------------------------
// Warp-per-node pull SpMM with csr-index prefetch pipeline.
// EPI=0: plain store. EPI=1 (F=32): z = sum*rs_in + b2 -> out0; t3=z*rs_out -> out1.
// ---------------------------------------------------------------------------
template<int F, int EPI>
__device__ __forceinline__ void spmm_phase(
    const float* __restrict__ tin, float* __restrict__ out0,
    const float* __restrict__ b2, float* __restrict__ out1)
{
    constexpr int C   = F / 4;           // lanes per edge
    constexpr int EPW = 32 / C;          // edges per warp-iteration
    const int lane  = threadIdx.x & 31;
    const int sub   = lane / C;
    const int laneC = lane % C;
    const int* csr = g_int + ICSR;
    const int warp0 = (blockIdx.x * 256 + threadIdx.x) >> 5;

    for (int gid = warp0; gid < NN; gid += GRIDSZ * 8) {
        int s0 = __ldg(&g_int[IOFFS + gid]);
        int s1 = __ldg(&g_int[IOFFS + gid + 1]);
        float4 acc = make_float4(0.f, 0.f, 0.f, 0.f);
        int j = s0 + sub;
        int idx = (j < s1) ? __ldg(&csr[j]) : 0;
        while (j < s1) {
            int cur = idx;
            int jn = j + EPW;
            idx = (jn < s1) ? __ldg(&csr[jn]) : 0;   // prefetch next index
            float4 v = __ldg((const float4*)(tin + (size_t)cur * F + 4 * laneC));
            acc.x += v.x; acc.y += v.y; acc.z += v.z; acc.w += v.w;
            j = jn;
        }
        #pragma unroll
        for (int o = 16; o >= C; o >>= 1) {
            acc.x += __shfl_down_sync(0xffffffffu, acc.x, o);
            acc.y += __shfl_down_sync(0xffffffffu, acc.y, o);
            acc.z += __shfl_down_sync(0xffffffffu, acc.z, o);
            acc.w += __shfl_down_sync(0xffffffffu, acc.w, o);
        }
        if (lane < C) {
            if (EPI == 0) {
                *(float4*)(out0 + (size_t)gid * F + 4 * laneC) = acc;
            } else {
                float rin  = g_scratch[OFF_RS_IN + gid];
                float rout = g_scratch[OFF_RS_OUT + gid];
                float4 b = __ldg((const float4*)&b2[4 * laneC]);
                float4 z;
                z.x = fmaf(acc.x, rin, b.x);
                z.y = fmaf(acc.y, rin, b.y);
                z.z = fmaf(acc.z, rin, b.z);
                z.w = fmaf(acc.w, rin, b.w);
                *(float4*)(out0 + (size_t)gid * F + 4 * laneC) = z;
                float4 t;
                t.x = z.x * rout; t.y = z.y * rout;
                t.z = z.z * rout; t.w = z.w * rout;
                *(float4*)(out1 + (size_t)gid * F + 4 * laneC) = t;
            }
        }
    }
}

// ---------------------------------------------------------------------------
// The whole pipeline as one persistent kernel with software grid barriers.
// ---------------------------------------------------------------------------
__global__ void __launch_bounds__(256, 2) fused_kernel(
    const float* __restrict__ features,
    const int* __restrict__ src, const int* __restrict__ dst,
    const float* __restrict__ W1, const float* __restrict__ b1,
    const float* __restrict__ W2, const float* __restrict__ b2,
    const float* __restrict__ W3, const float* __restrict__ b3,
    float* __restrict__ z_out, float* __restrict__ recon)
{
    __shared__ float smem[9472];         // 37888 B: max over gemm configs
    const int tid = threadIdx.x;
    const int bid = blockIdx.x;
    const int gtid = bid * 256 + tid;

    // ---- Phase 1: zero degree counters ----
    for (int i = gtid; i < 100000; i += GRIDSZ * 256) g_int[i] = 0;
    grid_sync();

    // ---- Phase 2: degree histograms ----
    for (int i = gtid; i < NE; i += GRIDSZ * 256) {
        atomicAdd(&g_int[ICNT_SRC + __ldg(&src[i])], 1);
        atomicAdd(&g_int[ICNT_DST + __ldg(&dst[i])], 1);
    }
    grid_sync();

    // ---- Phase 3: rsqrt norms + scan block sums (L2-only loads after atomics) ----
    if (bid < NBLK) {
        int i = bid * 256 + tid;
        int v = 0;
        if (i < NN) {
            v = __ldcg(&g_int[ICNT_DST + i]);
            g_scratch[OFF_RS_IN  + i] = rsqrtf(fmaxf((float)v, 1.0f));
            g_scratch[OFF_RS_OUT + i] =
                rsqrtf(fmaxf((float)__ldcg(&g_int[ICNT_SRC + i]), 1.0f));
        }
        int s = v;
        #pragma unroll
        for (int o = 16; o; o >>= 1) s += __shfl_down_sync(0xffffffffu, s, o);
        int* ws = (int*)smem;
        if ((tid & 31) == 0) ws[tid >> 5] = s;
        __syncthreads();
        if (tid == 0) {
            int r = 0;
            #pragma unroll
            for (int k = 0; k < 8; k++) r += ws[k];
            g_int[IBSUM + bid] = r;
        }
    }
    grid_sync();

    // ---- Phase 4: scan the 196 block sums (block 0 only) -> IBASE ----
    if (bid == 0) {
        int v = (tid < NBLK) ? g_int[IBSUM + tid] : 0;
        int lane = tid & 31, w = tid >> 5;
        int x = v;
        #pragma unroll
        for (int o = 1; o < 32; o <<= 1) {
            int y = __shfl_up_sync(0xffffffffu, x, o);
            if (lane >= o) x += y;
        }
        int* ws = (int*)smem;
        int* wb = ws + 8;
        if (lane == 31) ws[w] = x;
        __syncthreads();
        if (tid == 0) {
            int r = 0;
            #pragma unroll
            for (int k = 0; k < 8; k++) { wb[k] = r; r += ws[k]; }
        }
        __syncthreads();
        if (tid < NBLK) g_int[IBASE + tid] = x - v + wb[w];
    }
    grid_sync();

    // ---- Phase 5: final exclusive offsets ----
    if (bid < NBLK) {
        int i = bid * 256 + tid;
        int v = (i < NN) ? __ldg(&g_int[ICNT_DST + i]) : 0;
        int lane = tid & 31, w = tid >> 5;
        int x = v;
        #pragma unroll
        for (int o = 1; o < 32; o <<= 1) {
            int y = __shfl_up_sync(0xffffffffu, x, o);
            if (lane >= o) x += y;
        }
        int* ws = (int*)smem;
        int* wb = ws + 8;
        if (lane == 31) ws[w] = x;
        __syncthreads();
        if (tid == 0) {
            int r = 0;
            #pragma unroll
            for (int k = 0; k < 8; k++) { wb[k] = r; r += ws[k]; }
        }
        __syncthreads();
        if (i < NN) g_int[IOFFS + i] = x - v + wb[w] + g_int[IBASE + bid];
    }
    if (gtid == 0) g_int[IOFFS + NN] = NE;
    grid_sync();

    // ---- Phase 6: CSR fill (consumes ICNT_DST) ----
    for (int i = gtid; i < NE; i += GRIDSZ * 256) {
        int s = __ldg(&src[i]);
        int d = __ldg(&dst[i]);
        int c = atomicSub(&g_int[ICNT_DST + d], 1);
        g_int[ICSR + g_int[IOFFS + d] + c - 1] = s;
    }
    grid_sync();

    // ---- Phase 7: gemm1  t1 = (X @ W1) * rs_out ----
    gemm_phase<128, 64, 32, 0, 1>(features, W1, nullptr, nullptr,
                                  g_scratch + OFF_RS_OUT, nullptr,
                                  g_scratch + OFF_T1, smem);
    grid_sync();

    // ---- Phase 8: agg1 = A t1 ----
    spmm_phase<64, 0>(g_scratch + OFF_T1, g_scratch + OFF_AGG1, nullptr, nullptr);
    grid_sync();

    // ---- Phase 9: gemm2  t2 = (relu(agg1*rs_in + b1) @ W2) * rs_out ----
    gemm_phase<64, 32, 32, 1, 1>(g_scratch + OFF_AGG1, W2,
                                 g_scratch + OFF_RS_IN, b1,
                                 g_scratch + OFF_RS_OUT, nullptr,
                                 g_scratch + OFF_T2, smem);
    grid_sync();

    // ---- Phase 10: z = (A t2)*rs_in + b2 -> z_out ; t3 = z*rs_out ----
    spmm_phase<32, 1>(g_scratch + OFF_T2, z_out, b2, g_scratch + OFF_T3);
    grid_sync();

    // ---- Phase 11: agg3 = A t3 ----
    spmm_phase<32, 0>(g_scratch + OFF_T3, g_scratch + OFF_AGG3, nullptr, nullptr);
    grid_sync();

    // ---- Phase 12: recon = (agg3*rs_in) @ W3 + b3 ----
    gemm_phase<32, 128, 32, 2, 2>(g_scratch + OFF_AGG3, W3,
                                  g_scratch + OFF_RS_IN, nullptr,
                                  nullptr, b3, recon, smem);
}

// ---------------------------------------------------------------------------
extern "C" void kernel_launch(void* const* d_in, const int* in_sizes, int n_in,
                              void* d_out, int out_size)
{
    const float* features = (const float*)d_in[0];
    const int*   src      = (const int*)d_in[1];
    const int*   dst      = (const int*)d_in[2];
    const float* W1       = (const float*)d_in[3];
    const float* b1       = (const float*)d_in[4];
    const float* W2       = (const float*)d_in[5];
    const float* b2       = (const float*)d_in[6];
    const float* W3       = (const float*)d_in[7];
    const float* b3       = (const float*)d_in[8];

    float* z_out = (float*)d_out;                    // [50000, 32]
    float* recon = (float*)d_out + (size_t)NN * 32;  // [50000, 128]

    fused_kernel<<<GRIDSZ, 256>>>(features, src, dst,
                                  W1, b1, W2, b2, W3, b3, z_out, recon);
}

// round 10
// speedup vs baseline: 1.4426x; 1.4426x over previous
#include <cuda_runtime.h>

// Problem constants
#define NN 50000
#define NE 600000
#define NBLK 196                     // ceil(NN/256)
#define GRIDB 592                    // 148 SMs x 4 blocks (csr_build kernel only)

// Float scratch offsets (no zeroing needed; fully overwritten each replay)
#define OFF_RS_OUT 0
#define OFF_RS_IN  50000
#define OFF_T1     100000            // 50000*64
#define OFF_AGG1   3300000           // 50000*64
#define OFF_T2     6500000           // 50000*32
#define OFF_T3     8100000           // 50000*32
#define OFF_AGG3   9700000           // 50000*32
#define SCRATCH_TOTAL 11300000       // 45.2 MB

// Int scratch offsets
#define ICNT_SRC 0                   // 50000 out-degree counts
#define ICNT_DST 50000               // 50000 in-degree counts (consumed by fill)
#define IOFFS    100000              // 50001 CSR row offsets
#define ICSR     150004              // 600000 src ids grouped by dst
#define IBSUM    750004              // 196 scan block sums
#define IBASE    750200              // 196 scan block bases
#define INT_TOTAL 750396

__device__ __align__(16) float g_scratch[SCRATCH_TOTAL];
__device__ __align__(16) int   g_int[INT_TOTAL];
__device__ unsigned g_bar_count;     // zero-init; returns to 0 after each barrier
__device__ unsigned g_bar_gen;       // monotonically increasing across replays

// ---------------------------------------------------------------------------
// Software grid barrier for the csr_build kernel (GRIDB co-resident blocks).
// ---------------------------------------------------------------------------
__device__ __forceinline__ void grid_sync() {
    __syncthreads();
    if (threadIdx.x == 0) {
        __threadfence();
        unsigned gen = atomicAdd(&g_bar_gen, 0u);      // read BEFORE arriving
        if (atomicAdd(&g_bar_count, 1u) == GRIDB - 1u) {
            atomicExch(&g_bar_count, 0u);
            __threadfence();
            atomicAdd(&g_bar_gen, 1u);                 // release
        } else {
            while (atomicAdd(&g_bar_gen, 0u) == gen) __nanosleep(64);
        }
        __threadfence();
    }
    __syncthreads();
}

// ---------------------------------------------------------------------------
// CSR build + norms, all six tiny phases in one persistent kernel.
// Lightweight: regs low, smem 64B -> 4 blocks/SM co-resident guaranteed.
// ---------------------------------------------------------------------------
__global__ void __launch_bounds__(256, 4) csr_build_kernel(
    const int* __restrict__ src, const int* __restrict__ dst)
{
    __shared__ int ws[8], wb[8];
    const int tid = threadIdx.x;
    const int bid = blockIdx.x;
    const int gtid = bid * 256 + tid;

    // ---- P1: zero degree counters (100k ints) ----
    for (int i = gtid; i < 100000; i += GRIDB * 256) g_int[i] = 0;
    grid_sync();

    // ---- P2: degree histograms ----
    for (int i = gtid; i < NE; i += GRIDB * 256) {
        atomicAdd(&g_int[ICNT_SRC + __ldg(&src[i])], 1);
        atomicAdd(&g_int[ICNT_DST + __ldg(&dst[i])], 1);
    }
    grid_sync();

    // ---- P3: rsqrt norms + per-256-chunk sums (L2-only loads after atomics) ----
    if (bid < NBLK) {
        int i = bid * 256 + tid;
        int v = 0;
        if (i < NN) {
            v = __ldcg(&g_int[ICNT_DST + i]);
            g_scratch[OFF_RS_IN  + i] = rsqrtf(fmaxf((float)v, 1.0f));
            g_scratch[OFF_RS_OUT + i] =
                rsqrtf(fmaxf((float)__ldcg(&g_int[ICNT_SRC + i]), 1.0f));
        }
        int s = v;
        #pragma unroll
        for (int o = 16; o; o >>= 1) s += __shfl_down_sync(0xffffffffu, s, o);
        if ((tid & 31) == 0) ws[tid >> 5] = s;
        __syncthreads();
        if (tid == 0) {
            int r = 0;
            #pragma unroll
            for (int k = 0; k < 8; k++) r += ws[k];
            g_int[IBSUM + bid] = r;
        }
    }
    grid_sync();

    // ---- P4: scan the 196 chunk sums (block 0) -> IBASE ----
    if (bid == 0) {
        int v = (tid < NBLK) ? __ldcg(&g_int[IBSUM + tid]) : 0;
        int lane = tid & 31, w = tid >> 5;
        int x = v;
        #pragma unroll
        for (int o = 1; o < 32; o <<= 1) {
            int y = __shfl_up_sync(0xffffffffu, x, o);
            if (lane >= o) x += y;
        }
        if (lane == 31) ws[w] = x;
        __syncthreads();
        if (tid == 0) {
            int r = 0;
            #pragma unroll
            for (int k = 0; k < 8; k++) { wb[k] = r; r += ws[k]; }
        }
        __syncthreads();
        if (tid < NBLK) g_int[IBASE + tid] = x - v + wb[w];
    }
    grid_sync();

    // ---- P5: final exclusive CSR offsets ----
    if (bid < NBLK) {
        int i = bid * 256 + tid;
        int v = (i < NN) ? __ldcg(&g_int[ICNT_DST + i]) : 0;
        int lane = tid & 31, w = tid >> 5;
        int x = v;
        #pragma unroll
        for (int o = 1; o < 32; o <<= 1) {
            int y = __shfl_up_sync(0xffffffffu, x, o);
            if (lane >= o) x += y;
        }
        if (lane == 31) ws[w] = x;
        __syncthreads();
        if (tid == 0) {
            int r = 0;
            #pragma unroll
            for (int k = 0; k < 8; k++) { wb[k] = r; r += ws[k]; }
        }
        __syncthreads();
        if (i < NN) g_int[IOFFS + i] = x - v + wb[w] + __ldcg(&g_int[IBASE + bid]);
    }
    if (gtid == 0) g_int[IOFFS + NN] = NE;
    grid_sync();

    // ---- P6: CSR fill (consumes ICNT_DST via atomicSub) ----
    for (int i = gtid; i < NE; i += GRIDB * 256) {
        int s = __ldg(&src[i]);
        int d = __ldg(&dst[i]);
        int c = atomicSub(&g_int[ICNT_DST + d], 1);
        g_int[ICSR + __ldcg(&g_int[IOFFS + d]) + c - 1] = s;
    }
}

// ---------------------------------------------------------------------------
// Warp-per-node pull SpMM (one warp per dst node; 32/(F/4) edges per iter;
// partials folded with shfl; single coalesced store).
// EPI=0: plain store. EPI=1 (F=32): z = sum*rs_in + b2 -> out0; t3=z*rs_out -> out1.
// ---------------------------------------------------------------------------
template<int F, int EPI>
__global__ void __launch_bounds__(256) pull_spmm(const float* __restrict__ tin,
                                                 float* __restrict__ out0,
                                                 const float* __restrict__ b2,
                                                 float* __restrict__ out1)
{
    constexpr int C   = F / 4;       // float4 chunks per row (lanes per edge)
    constexpr int EPW = 32 / C;      // edges processed per warp-iteration
    int gid = (blockIdx.x * 256 + threadIdx.x) >> 5;   // warp id = node id
    if (gid >= NN) return;
    int lane  = threadIdx.x & 31;
    int sub   = lane / C;
    int laneC = lane % C;

    int s0 = __ldg(&g_int[IOFFS + gid]);
    int s1 = __ldg(&g_int[IOFFS + gid + 1]);
    const int* csr = g_int + ICSR;

    float4 acc = make_float4(0.f, 0.f, 0.f, 0.f);
    for (int j = s0 + sub; j < s1; j += EPW) {
        int sidx = __ldg(&csr[j]);
        float4 v = __ldg((const float4*)(tin + (size_t)sidx * F + 4 * laneC));
        acc.x += v.x; acc.y += v.y; acc.z += v.z; acc.w += v.w;
    }
    #pragma unroll
    for (int o = 16; o >= C; o >>= 1) {
        acc.x += __shfl_down_sync(0xffffffffu, acc.x, o);
        acc.y += __shfl_down_sync(0xffffffffu, acc.y, o);
        acc.z += __shfl_down_sync(0xffffffffu, acc.z, o);
        acc.w += __shfl_down_sync(0xffffffffu, acc.w, o);
    }
    if (lane < C) {
        if (EPI == 0) {
            *(float4*)(out0 + (size_t)gid * F + 4 * laneC) = acc;
        } else {
            float rin  = g_scratch[OFF_RS_IN + gid];
            float rout = g_scratch[OFF_RS_OUT + gid];
            float4 b = __ldg((const float4*)&b2[4 * laneC]);
            float4 z;
            z.x = fmaf(acc.x, rin, b.x);
            z.y = fmaf(acc.y, rin, b.y);
            z.z = fmaf(acc.z, rin, b.z);
            z.w = fmaf(acc.w, rin, b.w);
            *(float4*)(out0 + (size_t)gid * F + 4 * laneC) = z;
            float4 t;
            t.x = z.x * rout; t.y = z.y * rout; t.z = z.z * rout; t.w = z.w * rout;
            *(float4*)(out1 + (size_t)gid * F + 4 * laneC) = t;
        }
    }
}

// ---------------------------------------------------------------------------
// Register-tiled GEMM, transposed X tile (conflict-free LDS.128 everywhere):
//   out[n, :J] = f_out( f_in(X[n, :K]) @ W )
//   MODE_IN : 0 raw, 1 relu(v*rs_in[n] + bin[k]), 2 v*rs_in[n]
//   MODE_OUT: 0 raw, 1 *rs_out[n],               2 +bout[j]
// ---------------------------------------------------------------------------
template<int K, int J, int KC, int TN, int MODE_IN, int MODE_OUT>
__global__ void __launch_bounds__(256) gemm_kernel(
    const float* __restrict__ X, const float* __restrict__ W,
    const float* __restrict__ rs_in, const float* __restrict__ bin,
    const float* __restrict__ rs_out, const float* __restrict__ bout,
    float* __restrict__ out)
{
    constexpr int JV = J / 8;            // column lanes (8 cols each)
    constexpr int NT = 256 / JV;         // thread rows
    constexpr int NB = NT * TN;          // nodes per block
    constexpr int XST = NB;              // transposed row stride

    __shared__ float sW[KC * J];
    __shared__ float sX[KC * XST];       // [k][node]
    __shared__ float sRS[NB];

    const int nrow = threadIdx.x / JV;
    const int jv   = threadIdx.x % JV;
    const int base = blockIdx.x * NB;

    if (MODE_OUT == 1 && threadIdx.x < NB) {
        int n = base + threadIdx.x;
        sRS[threadIdx.x] = (n < NN) ? __ldg(&rs_out[n]) : 0.f;
    }

    float4 acc[TN][2];
    #pragma unroll
    for (int t = 0; t < TN; t++)
        #pragma unroll
        for (int c = 0; c < 2; c++) {
            if (MODE_OUT == 2) acc[t][c] = __ldg((const float4*)&bout[8 * jv + 4 * c]);
            else               acc[t][c] = make_float4(0.f, 0.f, 0.f, 0.f);
        }

    #pragma unroll 1
    for (int k0 = 0; k0 < K; k0 += KC) {
        __syncthreads();
        for (int i = threadIdx.x; i < KC * J / 4; i += 256)
            ((float4*)sW)[i] = __ldg(&((const float4*)(W + (size_t)k0 * J))[i]);
        for (int i = threadIdx.x; i < NB * (KC / 4); i += 256) {
            int nl = i % NB;
            int kc = i / NB;
            int n = base + nl;
            float4 v = make_float4(0.f, 0.f, 0.f, 0.f);
            if (n < NN) {
                v = __ldg((const float4*)&X[(size_t)n * K + k0 + 4 * kc]);
                if (MODE_IN == 1) {
                    float r = __ldg(&rs_in[n]);
                    float4 b = __ldg((const float4*)&bin[k0 + 4 * kc]);
                    v.x = fmaxf(fmaf(v.x, r, b.x), 0.f);
                    v.y = fmaxf(fmaf(v.y, r, b.y), 0.f);
                    v.z = fmaxf(fmaf(v.z, r, b.z), 0.f);
                    v.w = fmaxf(fmaf(v.w, r, b.w), 0.f);
                } else if (MODE_IN == 2) {
                    float r = __ldg(&rs_in[n]);
                    v.x *= r; v.y *= r; v.z *= r; v.w *= r;
                }
            }
            sX[(4 * kc + 0) * XST + nl] = v.x;
            sX[(4 * kc + 1) * XST + nl] = v.y;
            sX[(4 * kc + 2) * XST + nl] = v.z;
            sX[(4 * kc + 3) * XST + nl] = v.w;
        }
        __syncthreads();

        #pragma unroll 4
        for (int k = 0; k < KC; k++) {
            float4 w0 = *(const float4*)&sW[k * J + 8 * jv];
            float4 w1 = *(const float4*)&sW[k * J + 8 * jv + 4];
            #pragma unroll
            for (int tt = 0; tt < TN / 4; tt++) {
                float4 xa = *(const float4*)&sX[k * XST + nrow * TN + 4 * tt];
                float xk4[4] = {xa.x, xa.y, xa.z, xa.w};
                #pragma unroll
                for (int q = 0; q < 4; q++) {
                    int t = 4 * tt + q;
                    float xk = xk4[q];
                    acc[t][0].x = fmaf(xk, w0.x, acc[t][0].x);
                    acc[t][0].y = fmaf(xk, w0.y, acc[t][0].y);
                    acc[t][0].z = fmaf(xk, w0.z, acc[t][0].z);
                    acc[t][0].w = fmaf(xk, w0.w, acc[t][0].w);
                    acc[t][1].x = fmaf(xk, w1.x, acc[t][1].x);
                    acc[t][1].y = fmaf(xk, w1.y, acc[t][1].y);
                    acc[t][1].z = fmaf(xk, w1.z, acc[t][1].z);
                    acc[t][1].w = fmaf(xk, w1.w, acc[t][1].w);
                }
            }
        }
    }

    #pragma unroll
    for (int t = 0; t < TN; t++) {
        int nl = nrow * TN + t;
        int n = base + nl;
        if (n < NN) {
            if (MODE_OUT == 1) {
                float r = sRS[nl];
                #pragma unroll
                for (int c = 0; c < 2; c++) {
                    acc[t][c].x *= r; acc[t][c].y *= r;
                    acc[t][c].z *= r; acc[t][c].w *= r;
                }
            }
            *(float4*)&out[(size_t)n * J + 8 * jv]     = acc[t][0];
            *(float4*)&out[(size_t)n * J + 8 * jv + 4] = acc[t][1];
        }
    }
}

// ---------------------------------------------------------------------------
extern "C" void kernel_launch(void* const* d_in, const int* in_sizes, int n_in,
                              void* d_out, int out_size)
{
    const float* features = (const float*)d_in[0];
    const int*   src      = (const int*)d_in[1];
    const int*   dst      = (const int*)d_in[2];
    const float* W1       = (const float*)d_in[3];
    const float* b1       = (const float*)d_in[4];
    const float* W2       = (const float*)d_in[5];
    const float* b2       = (const float*)d_in[6];
    const float* W3       = (const float*)d_in[7];
    const float* b3       = (const float*)d_in[8];

    float* z_out = (float*)d_out;                    // [50000, 32]
    float* recon = (float*)d_out + (size_t)NN * 32;  // [50000, 128]

    float* sp = nullptr;
    cudaGetSymbolAddress((void**)&sp, g_scratch);
    float* rs_out = sp + OFF_RS_OUT;
    float* rs_in  = sp + OFF_RS_IN;
    float* t1     = sp + OFF_T1;
    float* agg1   = sp + OFF_AGG1;
    float* t2     = sp + OFF_T2;
    float* t3     = sp + OFF_T3;
    float* agg3   = sp + OFF_AGG3;

    const int TB = 256;
    const int SPMM_BLKS = (NN * 32 + TB - 1) / TB;   // one warp per node

    // 1) CSR build + norms: one persistent kernel, six internal phases
    csr_build_kernel<<<GRIDB, TB>>>(src, dst);

    // 2) Layer 1: t1 = (X @ W1) * rs_out ; agg1 = A t1   (TN=8, NB=256)
    gemm_kernel<128, 64, 32, 8, 0, 1><<<(NN + 255) / 256, TB>>>(
        features, W1, nullptr, nullptr, rs_out, nullptr, t1);
    pull_spmm<64, 0><<<SPMM_BLKS, TB>>>(t1, agg1, nullptr, nullptr);

    // 3) Layer 2: t2 = (relu(agg1*rs_in + b1) @ W2) * rs_out (TN=4, NB=256)
    //    then fused pull: z = (A t2)*rs_in + b2 -> z_out ; t3 = z*rs_out
    gemm_kernel<64, 32, 32, 4, 1, 1><<<(NN + 255) / 256, TB>>>(
        agg1, W2, rs_in, b1, rs_out, nullptr, t2);
    pull_spmm<32, 1><<<SPMM_BLKS, TB>>>(t2, z_out, b2, t3);

    // 4) Layer 3: agg3 = A t3 ; recon = (agg3*rs_in) @ W3 + b3 (TN=8, NB=128)
    pull_spmm<32, 0><<<SPMM_BLKS, TB>>>(t3, agg3, nullptr, nullptr);
    gemm_kernel<32, 128, 32, 8, 2, 2><<<(NN + 127) / 128, TB>>>(
        agg3, W3, rs_in, nullptr, nullptr, b3, recon);
}